// round 10
// baseline (speedup 1.0000x reference)
#include <cuda_runtime.h>
#include <cstdint>

#define IN_COLS      8192
#define N_ROWS       8192
#define MAX_SLICES   1024
#define MAX_OUT_COLS 16384
#define ROWS_PER_BLK 16
#define GTHREADS     256
#define BTHREADS     1024

// out-col -> in-col map.
__device__ __align__(16) int g_col_idx[MAX_OUT_COLS];

// Parallel build: one block per 256-column output window. Fires the PDL
// trigger immediately; scan via shfl, per-column binary search in smem.
__global__ void __launch_bounds__(BTHREADS)
build_col_idx_kernel(const int* __restrict__ slices_raw, int n_slices, int out_cols) {
    cudaTriggerProgrammaticLaunchCompletion();

    __shared__ int s_cum[MAX_SLICES];
    __shared__ int s_start[MAX_SLICES];
    __shared__ int s_wsum[BTHREADS / 32];
    __shared__ int s_is64;

    int t = threadIdx.x;

    if (t == 0) {
        // int64 LE: odd 32-bit words are zero high-halves; int32: odd words are ends >= 1.
        int z = 0;
        for (int k = 0; k < 4 && k < n_slices; k++)
            z |= slices_raw[4 * k + 1] | slices_raw[4 * k + 3];
        s_is64 = (z == 0) ? 1 : 0;
    }
    __syncthreads();
    int is64 = s_is64;

    int st = 0, len = 0;
    if (t < n_slices) {
        if (is64) { st = __ldg(&slices_raw[4 * t]); len = __ldg(&slices_raw[4 * t + 2]) - st; }
        else      { st = __ldg(&slices_raw[2 * t]); len = __ldg(&slices_raw[2 * t + 1]) - st; }
    }

    int lane = t & 31, wid = t >> 5;
    int v = len;
    #pragma unroll
    for (int d = 1; d < 32; d <<= 1) {
        int n = __shfl_up_sync(0xFFFFFFFFu, v, d);
        if (lane >= d) v += n;
    }
    if (lane == 31) s_wsum[wid] = v;
    __syncthreads();
    if (wid == 0) {
        int w = (lane < BTHREADS / 32) ? s_wsum[lane] : 0;
        #pragma unroll
        for (int d = 1; d < BTHREADS / 32; d <<= 1) {
            int n = __shfl_up_sync(0xFFFFFFFFu, w, d);
            if (lane >= d) w += n;
        }
        if (lane < BTHREADS / 32) s_wsum[lane] = w;
    }
    __syncthreads();
    int incl = v + ((wid > 0) ? s_wsum[wid - 1] : 0);

    if (t < n_slices) { s_cum[t] = incl; s_start[t] = st; }
    __syncthreads();

    if (t < GTHREADS) {
        int p = blockIdx.x * GTHREADS + t;
        if (p < out_cols) {
            int lo = 0, hi = n_slices - 1;
            while (lo < hi) {
                int mid = (lo + hi) >> 1;
                if (s_cum[mid] > p) hi = mid; else lo = mid + 1;
            }
            int base = (lo == 0) ? 0 : s_cum[lo - 1];
            g_col_idx[p] = s_start[lo] + (p - base);
        }
    }
}

// Gather with smem transpose: scalar warp-contiguous loads (proven pattern),
// then float4 stores via a 256x16 smem tile -> 4x fewer store wavefronts.
__global__ void __launch_bounds__(GTHREADS)
gather_kernel(const float* __restrict__ in, float* __restrict__ out, int out_cols) {
    __shared__ float s_tile[ROWS_PER_BLK * GTHREADS];   // [row][col] 16 KB

    int t  = threadIdx.x;
    int p0 = blockIdx.x * GTHREADS;
    int r0 = blockIdx.y * ROWS_PER_BLK;
    int w  = out_cols - p0; if (w > GTHREADS) w = GTHREADS;

    cudaGridDependencySynchronize();

    // Phase 1: gather loads (one col per thread, 16 rows), park in smem.
    if (t < w) {
        int idx = g_col_idx[p0 + t];
        const float* src = in + (size_t)r0 * IN_COLS + idx;
        float v[ROWS_PER_BLK];
        #pragma unroll
        for (int j = 0; j < ROWS_PER_BLK; j++)
            v[j] = __ldg(src + (size_t)j * IN_COLS);
        #pragma unroll
        for (int j = 0; j < ROWS_PER_BLK; j++)
            s_tile[j * GTHREADS + t] = v[j];
    }
    __syncthreads();

    // Phase 2: vectorized stores. quads consecutive across threads -> STG.128 coalesced.
    float* dstBase = out + (size_t)r0 * out_cols + p0;
    if (w == GTHREADS) {
        // Main case: 64 quads x 16 rows = 1024 quad-stores, 4 per thread.
        #pragma unroll
        for (int k = 0; k < 4; k++) {
            int i = k * GTHREADS + t;
            int q = i & 63;          // quad within row
            int r = i >> 6;          // row
            float4 val = *(const float4*)&s_tile[r * GTHREADS + (q << 2)];
            asm volatile("st.global.cs.v4.f32 [%0], {%1,%2,%3,%4};"
                         :: "l"(dstBase + (size_t)r * out_cols + (q << 2)),
                            "f"(val.x), "f"(val.y), "f"(val.z), "f"(val.w) : "memory");
        }
    } else {
        // Tail window: w % 4 == 0 here (out_cols divisible by 4), generic loop.
        int quads = w >> 2;
        for (int i = t; i < quads * ROWS_PER_BLK; i += GTHREADS) {
            int q = i % quads;
            int r = i / quads;
            float4 val = *(const float4*)&s_tile[r * GTHREADS + (q << 2)];
            asm volatile("st.global.cs.v4.f32 [%0], {%1,%2,%3,%4};"
                         :: "l"(dstBase + (size_t)r * out_cols + (q << 2)),
                            "f"(val.x), "f"(val.y), "f"(val.z), "f"(val.w) : "memory");
        }
        // Scalar remainder (unused when out_cols % 4 == 0).
        for (int c = quads * 4 + t; c < w; c += GTHREADS)
            for (int r = 0; r < ROWS_PER_BLK; r++)
                dstBase[(size_t)r * out_cols + c] = s_tile[r * GTHREADS + c];
    }
}

extern "C" void kernel_launch(void* const* d_in, const int* in_sizes, int n_in,
                              void* d_out, int out_size) {
    const float* input      = (const float*)d_in[0];
    const int*   slices_raw = (const int*)d_in[1];
    float*       out        = (float*)d_out;

    int n_slices = in_sizes[1] / 2;      // 600
    int out_cols = out_size / N_ROWS;    // 12500

    int nwin = (out_cols + GTHREADS - 1) / GTHREADS;   // 49
    build_col_idx_kernel<<<nwin, BTHREADS>>>(slices_raw, n_slices, out_cols);

    cudaLaunchConfig_t cfg = {};
    cfg.gridDim  = dim3(nwin, N_ROWS / ROWS_PER_BLK, 1);
    cfg.blockDim = dim3(GTHREADS, 1, 1);
    cfg.dynamicSmemBytes = 0;
    cfg.stream = 0;
    cudaLaunchAttribute attr[1];
    attr[0].id = cudaLaunchAttributeProgrammaticStreamSerialization;
    attr[0].val.programmaticStreamSerializationAllowed = 1;
    cfg.attrs = attr;
    cfg.numAttrs = 1;
    cudaLaunchKernelEx(&cfg, gather_kernel, input, out, out_cols);
}

// round 11
// speedup vs baseline: 1.5920x; 1.5920x over previous
#include <cuda_runtime.h>
#include <cstdint>

#define IN_COLS      8192
#define N_ROWS       8192
#define MAX_SLICES   1024
#define MAX_OUT_COLS 16384
#define ROWS_PER_BLK 16
#define GTHREADS     256
#define BTHREADS     1024

// out-col -> in-col map.
__device__ __align__(16) int g_col_idx[MAX_OUT_COLS];

// Parallel build: one block per 256-column output window. Fires the PDL
// trigger immediately; shfl-based scan of slice lengths, then each of the
// first 256 threads binary-searches its own column's owning slice in smem.
__global__ void __launch_bounds__(BTHREADS)
build_col_idx_kernel(const int* __restrict__ slices_raw, int n_slices, int out_cols) {
    cudaTriggerProgrammaticLaunchCompletion();

    __shared__ int s_cum[MAX_SLICES];    // inclusive prefix of lengths
    __shared__ int s_start[MAX_SLICES];
    __shared__ int s_wsum[BTHREADS / 32];
    __shared__ int s_is64;

    int t = threadIdx.x;

    if (t == 0) {
        // int64 LE: odd 32-bit words are zero high-halves; int32: odd words are ends >= 1.
        int z = 0;
        for (int k = 0; k < 4 && k < n_slices; k++)
            z |= slices_raw[4 * k + 1] | slices_raw[4 * k + 3];
        s_is64 = (z == 0) ? 1 : 0;
    }
    __syncthreads();
    int is64 = s_is64;

    int st = 0, len = 0;
    if (t < n_slices) {
        if (is64) { st = __ldg(&slices_raw[4 * t]); len = __ldg(&slices_raw[4 * t + 2]) - st; }
        else      { st = __ldg(&slices_raw[2 * t]); len = __ldg(&slices_raw[2 * t + 1]) - st; }
    }

    // Two-level shfl scan (inclusive).
    int lane = t & 31, wid = t >> 5;
    int v = len;
    #pragma unroll
    for (int d = 1; d < 32; d <<= 1) {
        int n = __shfl_up_sync(0xFFFFFFFFu, v, d);
        if (lane >= d) v += n;
    }
    if (lane == 31) s_wsum[wid] = v;
    __syncthreads();
    if (wid == 0) {
        int w = (lane < BTHREADS / 32) ? s_wsum[lane] : 0;
        #pragma unroll
        for (int d = 1; d < BTHREADS / 32; d <<= 1) {
            int n = __shfl_up_sync(0xFFFFFFFFu, w, d);
            if (lane >= d) w += n;
        }
        if (lane < BTHREADS / 32) s_wsum[lane] = w;
    }
    __syncthreads();
    int incl = v + ((wid > 0) ? s_wsum[wid - 1] : 0);

    if (t < n_slices) { s_cum[t] = incl; s_start[t] = st; }
    __syncthreads();

    if (t < GTHREADS) {
        int p = blockIdx.x * GTHREADS + t;
        if (p < out_cols) {
            int lo = 0, hi = n_slices - 1;
            while (lo < hi) {                    // first i with s_cum[i] > p
                int mid = (lo + hi) >> 1;
                if (s_cum[mid] > p) hi = mid; else lo = mid + 1;
            }
            int base = (lo == 0) ? 0 : s_cum[lo - 1];
            g_col_idx[p] = s_start[lo] + (p - base);
        }
    }
}

// Scalar gather (proven optimum shape): one output column per thread
// (warp-contiguous index stream), 16 rows per thread, plain stores.
// PDL: preamble runs while build drains; parks on grid dependency before
// consuming g_col_idx.
__global__ void __launch_bounds__(GTHREADS)
gather_kernel(const float* __restrict__ in, float* __restrict__ out, int out_cols) {
    int p  = blockIdx.x * GTHREADS + threadIdx.x;
    int r0 = blockIdx.y * ROWS_PER_BLK;

    const float* srcRow = in  + (size_t)r0 * IN_COLS;
    float*       dst    = out + (size_t)r0 * out_cols + p;

    cudaGridDependencySynchronize();

    if (p >= out_cols) return;
    int idx = g_col_idx[p];
    const float* src = srcRow + idx;

    #pragma unroll
    for (int j = 0; j < ROWS_PER_BLK; j++)
        dst[(size_t)j * out_cols] = __ldg(src + (size_t)j * IN_COLS);
}

extern "C" void kernel_launch(void* const* d_in, const int* in_sizes, int n_in,
                              void* d_out, int out_size) {
    const float* input      = (const float*)d_in[0];
    const int*   slices_raw = (const int*)d_in[1];
    float*       out        = (float*)d_out;

    int n_slices = in_sizes[1] / 2;      // 600
    int out_cols = out_size / N_ROWS;    // 12500

    int nwin = (out_cols + GTHREADS - 1) / GTHREADS;   // 49
    build_col_idx_kernel<<<nwin, BTHREADS>>>(slices_raw, n_slices, out_cols);

    cudaLaunchConfig_t cfg = {};
    cfg.gridDim  = dim3(nwin, N_ROWS / ROWS_PER_BLK, 1);
    cfg.blockDim = dim3(GTHREADS, 1, 1);
    cfg.dynamicSmemBytes = 0;
    cfg.stream = 0;
    cudaLaunchAttribute attr[1];
    attr[0].id = cudaLaunchAttributeProgrammaticStreamSerialization;
    attr[0].val.programmaticStreamSerializationAllowed = 1;
    cfg.attrs = attr;
    cfg.numAttrs = 1;
    cudaLaunchKernelEx(&cfg, gather_kernel, input, out, out_cols);
}